// round 1
// baseline (speedup 1.0000x reference)
#include <cuda_runtime.h>
#include <math.h>

#define N_NODES 50000
#define F_IN    128
#define H_DIM   64
#define C_DIM   32

// ---------------- scratch (no allocations allowed) ----------------
__device__ float g_dis [N_NODES];                 // deg -> rsqrt(deg)
__device__ float g_hs1 [N_NODES * H_DIM];         // (x@W1)*dis
__device__ float g_agg1[N_NODES * H_DIM];         // edge-sum of hs1
__device__ float g_hs2 [N_NODES * C_DIM];         // (h@W2)*dis
__device__ float g_agg2[N_NODES * C_DIM];         // edge-sum of hs2
__device__ int   g_is64;

// ---------------- edge index dtype detection ----------------
// jax.random.randint(dtype=int64) silently becomes int32 when x64 is off.
// If int64: every odd 32-bit word is a high word of a value < 50000 -> 0.
// If int32: odd words are random indices; P(256 of them all zero) ~ 0.
__global__ void detect_kernel(const int* __restrict__ ei) {
    __shared__ int s_nonzero;
    if (threadIdx.x == 0) s_nonzero = 0;
    __syncthreads();
    if (ei[2 * threadIdx.x + 1] != 0) atomicOr(&s_nonzero, 1);
    __syncthreads();
    if (threadIdx.x == 0) g_is64 = (s_nonzero == 0) ? 1 : 0;
}

__device__ __forceinline__ int edge_idx(const void* ei, long long E, int row,
                                        long long e, int is64) {
    if (is64) return (int)((const long long*)ei)[(long long)row * E + e];
    return ((const int*)ei)[(long long)row * E + e];
}

// ---------------- init: deg = 1 (self loop), zero aggregators ----------------
__global__ void init_kernel() {
    long long n = (long long)N_NODES * H_DIM;
    long long stride = (long long)gridDim.x * blockDim.x;
    for (long long i = (long long)blockIdx.x * blockDim.x + threadIdx.x; i < n; i += stride) {
        g_agg1[i] = 0.f;
        if (i < (long long)N_NODES * C_DIM) g_agg2[i] = 0.f;
        if (i < N_NODES) g_dis[i] = 1.0f;
    }
}

// ---------------- degree count over dst ----------------
__global__ void deg_kernel(const void* __restrict__ ei, long long E) {
    int is64 = g_is64;
    long long stride = (long long)gridDim.x * blockDim.x;
    for (long long e = (long long)blockIdx.x * blockDim.x + threadIdx.x; e < E; e += stride) {
        int d = edge_idx(ei, E, 1, e, is64);
        atomicAdd(&g_dis[d], 1.0f);   // compiles to RED (no return use)
    }
}

__global__ void rsqrt_kernel() {
    int i = blockIdx.x * blockDim.x + threadIdx.x;
    if (i < N_NODES) g_dis[i] = rsqrtf(g_dis[i]);  // deg >= 1 always
}

// ---------------- GEMM1: hs1 = (x @ W1) * dis, warp-per-row ----------------
__global__ void gemm1_kernel(const float* __restrict__ x, const float* __restrict__ W1) {
    __shared__ float sW[F_IN * H_DIM];  // 32 KB
    for (int i = threadIdx.x; i < F_IN * H_DIM; i += blockDim.x) sW[i] = W1[i];
    __syncthreads();
    int warp = threadIdx.x >> 5, lane = threadIdx.x & 31;
    int nwarps = blockDim.x >> 5;
    for (int r = blockIdx.x * nwarps + warp; r < N_NODES; r += gridDim.x * nwarps) {
        const float* xr = x + (long long)r * F_IN;
        float a0 = 0.f, a1 = 0.f;
        #pragma unroll 8
        for (int k = 0; k < F_IN; k++) {
            float xv = __ldg(xr + k);               // warp-broadcast load
            a0 += xv * sW[k * H_DIM + lane];
            a1 += xv * sW[k * H_DIM + lane + 32];
        }
        float d = g_dis[r];
        long long base = (long long)r * H_DIM;
        g_hs1[base + lane]      = a0 * d;
        g_hs1[base + lane + 32] = a1 * d;
    }
}

// ---------------- scatter1: agg1[dst] += hs1[src]  (warp-per-edge, red.v2) ----------------
__global__ void scatter1_kernel(const void* __restrict__ ei, long long E) {
    int is64 = g_is64;
    int lane = threadIdx.x & 31;
    long long w  = (long long)blockIdx.x * (blockDim.x >> 5) + (threadIdx.x >> 5);
    long long nw = (long long)gridDim.x * (blockDim.x >> 5);
    for (long long e = w; e < E; e += nw) {
        int s = edge_idx(ei, E, 0, e, is64);
        int d = edge_idx(ei, E, 1, e, is64);
        float2 v = ((const float2*)(g_hs1 + (long long)s * H_DIM))[lane];
        float* dst = g_agg1 + (long long)d * H_DIM + lane * 2;
        asm volatile("red.global.add.v2.f32 [%0], {%1, %2};"
                     :: "l"(dst), "f"(v.x), "f"(v.y) : "memory");
    }
}

// ---------------- fused: h = tanh(dis*(agg1+hs1)) -> d_out ; hs2 = (h@W2)*dis ----------------
__global__ void fuse_kernel(const float* __restrict__ W2, float* __restrict__ h_out) {
    __shared__ float sW[H_DIM * C_DIM];   // 8 KB
    __shared__ float sh[8][H_DIM];        // one h row per warp
    for (int i = threadIdx.x; i < H_DIM * C_DIM; i += blockDim.x) sW[i] = W2[i];
    __syncthreads();
    int warp = threadIdx.x >> 5, lane = threadIdx.x & 31;
    int nwarps = blockDim.x >> 5;
    for (int r = blockIdx.x * nwarps + warp; r < N_NODES; r += gridDim.x * nwarps) {
        float d = g_dis[r];
        long long base = (long long)r * H_DIM;
        float h0 = tanhf(d * (g_agg1[base + lane]      + g_hs1[base + lane]));
        float h1 = tanhf(d * (g_agg1[base + lane + 32] + g_hs1[base + lane + 32]));
        sh[warp][lane]      = h0;
        sh[warp][lane + 32] = h1;
        h_out[base + lane]      = h0;        // h is part of the output tuple
        h_out[base + lane + 32] = h1;
        __syncwarp();
        float acc = 0.f;
        #pragma unroll
        for (int k = 0; k < H_DIM; k++)
            acc += sh[warp][k] * sW[k * C_DIM + lane];
        g_hs2[(long long)r * C_DIM + lane] = acc * d;
        __syncwarp();
    }
}

// ---------------- scatter2: agg2[dst] += hs2[src]  (2 edges per warp) ----------------
__global__ void scatter2_kernel(const void* __restrict__ ei, long long E) {
    int is64 = g_is64;
    int lane = threadIdx.x & 31;
    int half = lane >> 4;      // which edge of the pair
    int l    = lane & 15;      // float2 slot within 32 floats
    long long w  = (long long)blockIdx.x * (blockDim.x >> 5) + (threadIdx.x >> 5);
    long long nw = (long long)gridDim.x * (blockDim.x >> 5);
    for (long long p = w; p * 2 < E; p += nw) {
        long long e = p * 2 + half;
        if (e < E) {
            int s = edge_idx(ei, E, 0, e, is64);
            int d = edge_idx(ei, E, 1, e, is64);
            float2 v = ((const float2*)(g_hs2 + (long long)s * C_DIM))[l];
            float* dst = g_agg2 + (long long)d * C_DIM + l * 2;
            asm volatile("red.global.add.v2.f32 [%0], {%1, %2};"
                         :: "l"(dst), "f"(v.x), "f"(v.y) : "memory");
        }
    }
}

// ---------------- final: out = dis*(agg2 + hs2) ----------------
__global__ void final_kernel(float* __restrict__ out) {
    long long n = (long long)N_NODES * C_DIM;
    long long stride = (long long)gridDim.x * blockDim.x;
    for (long long i = (long long)blockIdx.x * blockDim.x + threadIdx.x; i < n; i += stride) {
        int r = (int)(i >> 5);             // C_DIM == 32
        out[i] = g_dis[r] * (g_agg2[i] + g_hs2[i]);
    }
}

// ---------------- launch ----------------
extern "C" void kernel_launch(void* const* d_in, const int* in_sizes, int n_in,
                              void* d_out, int out_size) {
    const float* x  = (const float*)d_in[0];
    const void*  ei = d_in[1];
    const float* W1 = (const float*)d_in[2];
    const float* W2 = (const float*)d_in[3];
    long long E = (long long)in_sizes[1] / 2;

    float* out_ptr = (float*)d_out;                      // [N, 32]
    float* h_ptr   = (float*)d_out + (long long)N_NODES * C_DIM;  // [N, 64]

    detect_kernel<<<1, 256>>>((const int*)ei);
    init_kernel<<<4096, 256>>>();
    deg_kernel<<<2048, 256>>>(ei, E);
    rsqrt_kernel<<<(N_NODES + 255) / 256, 256>>>();
    gemm1_kernel<<<(N_NODES + 7) / 8, 256>>>(x, W1);
    {
        long long blocks = (E + 7) / 8;                  // warp per edge, 8 warps/block
        scatter1_kernel<<<(unsigned)blocks, 256>>>(ei, E);
    }
    fuse_kernel<<<(N_NODES + 7) / 8, 256>>>(W2, h_ptr);
    {
        long long blocks = (E + 15) / 16;                // 2 edges per warp
        scatter2_kernel<<<(unsigned)blocks, 256>>>(ei, E);
    }
    final_kernel<<<2048, 256>>>(out_ptr);
}

// round 3
// speedup vs baseline: 1.3754x; 1.3754x over previous
#include <cuda_runtime.h>
#include <math.h>

#define N_NODES 50000
#define F_IN    128
#define H_DIM   64
#define C_DIM   32
#define E_MAX   1600000

// ---------------- scratch (no allocations allowed) ----------------
__device__ float g_dis [N_NODES];                 // degree (incl. self loop); consumers take rsqrtf inline
__device__ int2  g_edge[E_MAX];                   // packed (src, dst) int32
__device__ float g_hs1 [N_NODES * H_DIM];         // (x@W1)*dis  (gather source, immutable)
__device__ float g_agg1[N_NODES * H_DIM];         // seeded with hs1, then edge-red
__device__ float g_hs2 [N_NODES * C_DIM];
__device__ float g_agg2[N_NODES * C_DIM];
__device__ int   g_is64;

// ---------------- edge index dtype detection ----------------
// jax without x64 silently downcasts int64->int32. If truly int64, every odd
// 32-bit word is the high word of a value < 50000 -> 0. If int32, odd words
// are random node ids; P(256 all zero) ~ 0.
__global__ void detect_kernel(const int* __restrict__ ei) {
    __shared__ int s_nonzero;
    if (threadIdx.x == 0) s_nonzero = 0;
    __syncthreads();
    if (ei[2 * threadIdx.x + 1] != 0) atomicOr(&s_nonzero, 1);
    __syncthreads();
    if (threadIdx.x == 0) g_is64 = (s_nonzero == 0) ? 1 : 0;
}

__global__ void init_dis_kernel() {
    int i = blockIdx.x * blockDim.x + threadIdx.x;
    if (i < N_NODES) g_dis[i] = 1.0f;              // self loop
}

// ---------------- convert to int32 pairs + degree count ----------------
__global__ void convert_deg_kernel(const void* __restrict__ ei, long long E) {
    int is64 = g_is64;
    long long stride = (long long)gridDim.x * blockDim.x;
    for (long long e = (long long)blockIdx.x * blockDim.x + threadIdx.x; e < E; e += stride) {
        int s, d;
        if (is64) {
            s = (int)((const long long*)ei)[e];
            d = (int)((const long long*)ei)[E + e];
        } else {
            s = ((const int*)ei)[e];
            d = ((const int*)ei)[E + e];
        }
        g_edge[e] = make_int2(s, d);
        atomicAdd(&g_dis[d], 1.0f);                // RED.ADD.F32
    }
}

// ---------------- GEMM1: hs1 = (x @ W1) * dis; agg1 seeded = hs1 ----------------
// 256 threads = 32-row tile; thread (ty,tx) computes cols [tx*8, tx*8+8).
__global__ void gemm1_kernel(const float* __restrict__ x, const float* __restrict__ W1) {
    __shared__ float sW[F_IN * H_DIM];             // 32 KB
    float4* sW4 = (float4*)sW;
    const float4* W4 = (const float4*)W1;
    for (int i = threadIdx.x; i < F_IN * H_DIM / 4; i += blockDim.x) sW4[i] = W4[i];
    __syncthreads();

    int ty = threadIdx.x >> 3;                     // row within tile (0..31)
    int tx = threadIdx.x & 7;                      // col group (0..7)
    int row = blockIdx.x * 32 + ty;
    if (row >= N_NODES) return;

    const float* xr = x + (long long)row * F_IN;
    float4 a0 = make_float4(0.f, 0.f, 0.f, 0.f);
    float4 a1 = make_float4(0.f, 0.f, 0.f, 0.f);
    int cb = (tx * 8) >> 2;                        // float4 column base
    #pragma unroll 4
    for (int k = 0; k < F_IN; k++) {
        float xv = __ldg(xr + k);
        float4 w0 = sW4[k * (H_DIM / 4) + cb];
        float4 w1 = sW4[k * (H_DIM / 4) + cb + 1];
        a0.x += xv * w0.x; a0.y += xv * w0.y; a0.z += xv * w0.z; a0.w += xv * w0.w;
        a1.x += xv * w1.x; a1.y += xv * w1.y; a1.z += xv * w1.z; a1.w += xv * w1.w;
    }
    float dis = rsqrtf(g_dis[row]);
    a0.x *= dis; a0.y *= dis; a0.z *= dis; a0.w *= dis;
    a1.x *= dis; a1.y *= dis; a1.z *= dis; a1.w *= dis;
    long long base = ((long long)row * H_DIM + tx * 8) >> 2;
    ((float4*)g_hs1 )[base]     = a0;  ((float4*)g_hs1 )[base + 1] = a1;
    ((float4*)g_agg1)[base]     = a0;  ((float4*)g_agg1)[base + 1] = a1;  // self-loop seed
}

// ---------------- scatter1: agg1[dst] += hs1[src], half-warp/edge, red.v4 ----------------
__global__ void scatter1_kernel(long long E) {
    int lane = threadIdx.x & 31;
    int half = lane >> 4;                          // edge within pair
    int l    = lane & 15;                          // float4 slot (16 x 16B = 64 floats)
    long long w      = (long long)blockIdx.x * (blockDim.x >> 5) + (threadIdx.x >> 5);
    long long stride = (long long)gridDim.x * (blockDim.x >> 5) * 2;
    for (long long e = w * 2 + half; e < E; e += stride) {
        int2 sd = __ldg(&g_edge[e]);
        float4 v = ((const float4*)(g_hs1 + (long long)sd.x * H_DIM))[l];
        float* dst = g_agg1 + (long long)sd.y * H_DIM + l * 4;
        asm volatile("red.global.add.v4.f32 [%0], {%1,%2,%3,%4};"
                     :: "l"(dst), "f"(v.x), "f"(v.y), "f"(v.z), "f"(v.w) : "memory");
    }
}

// ---------------- fuse: h = tanh(dis*agg1) -> d_out; hs2 = (h@W2)*dis (2 rows/warp) ----------------
__global__ void fuse_kernel(const float* __restrict__ W2, float* __restrict__ h_out) {
    __shared__ float sW[H_DIM * C_DIM];            // 8 KB
    __shared__ float sh[8][2][H_DIM];              // 4 KB
    for (int i = threadIdx.x; i < H_DIM * C_DIM; i += blockDim.x) sW[i] = W2[i];
    __syncthreads();
    int warp = threadIdx.x >> 5, lane = threadIdx.x & 31;
    int r0 = (blockIdx.x * 8 + warp) * 2;
    if (r0 >= N_NODES) return;

    float dis0 = rsqrtf(g_dis[r0]);
    float dis1 = (r0 + 1 < N_NODES) ? rsqrtf(g_dis[r0 + 1]) : 0.f;
    {
        long long b0 = (long long)r0 * H_DIM;
        float h0 = tanhf(dis0 * g_agg1[b0 + lane]);
        float h1 = tanhf(dis0 * g_agg1[b0 + lane + 32]);
        sh[warp][0][lane] = h0;  sh[warp][0][lane + 32] = h1;
        h_out[b0 + lane] = h0;   h_out[b0 + lane + 32] = h1;
        if (r0 + 1 < N_NODES) {
            long long b1 = b0 + H_DIM;
            float g0 = tanhf(dis1 * g_agg1[b1 + lane]);
            float g1 = tanhf(dis1 * g_agg1[b1 + lane + 32]);
            sh[warp][1][lane] = g0;  sh[warp][1][lane + 32] = g1;
            h_out[b1 + lane] = g0;   h_out[b1 + lane + 32] = g1;
        }
    }
    __syncwarp();
    float acc0 = 0.f, acc1 = 0.f;
    #pragma unroll
    for (int k = 0; k < H_DIM; k++) {
        float wv = sW[k * C_DIM + lane];
        acc0 += sh[warp][0][k] * wv;               // sh reads are warp-broadcast
        acc1 += sh[warp][1][k] * wv;
    }
    float v0 = acc0 * dis0;
    g_hs2[(long long)r0 * C_DIM + lane] = v0;
    g_agg2[(long long)r0 * C_DIM + lane] = v0;     // self-loop seed
    if (r0 + 1 < N_NODES) {
        float v1 = acc1 * dis1;
        g_hs2[(long long)(r0 + 1) * C_DIM + lane] = v1;
        g_agg2[(long long)(r0 + 1) * C_DIM + lane] = v1;
    }
}

// ---------------- scatter2: agg2[dst] += hs2[src], 4 edges/warp, red.v4 ----------------
__global__ void scatter2_kernel(long long E) {
    int lane = threadIdx.x & 31;
    int q = lane >> 3;                             // edge within quad
    int l = lane & 7;                              // float4 slot (8 x 16B = 32 floats)
    long long w      = (long long)blockIdx.x * (blockDim.x >> 5) + (threadIdx.x >> 5);
    long long stride = (long long)gridDim.x * (blockDim.x >> 5) * 4;
    for (long long e = w * 4 + q; e < E; e += stride) {
        int2 sd = __ldg(&g_edge[e]);
        float4 v = ((const float4*)(g_hs2 + (long long)sd.x * C_DIM))[l];
        float* dst = g_agg2 + (long long)sd.y * C_DIM + l * 4;
        asm volatile("red.global.add.v4.f32 [%0], {%1,%2,%3,%4};"
                     :: "l"(dst), "f"(v.x), "f"(v.y), "f"(v.z), "f"(v.w) : "memory");
    }
}

// ---------------- final: out = dis * agg2 ----------------
__global__ void final_kernel(float* __restrict__ out) {
    long long i = (long long)blockIdx.x * blockDim.x + threadIdx.x;
    if (i < (long long)N_NODES * C_DIM) {
        int r = (int)(i >> 5);                     // C_DIM == 32
        out[i] = rsqrtf(g_dis[r]) * g_agg2[i];
    }
}

// ---------------- launch ----------------
extern "C" void kernel_launch(void* const* d_in, const int* in_sizes, int n_in,
                              void* d_out, int out_size) {
    const float* x  = (const float*)d_in[0];
    const void*  ei = d_in[1];
    const float* W1 = (const float*)d_in[2];
    const float* W2 = (const float*)d_in[3];
    long long E = (long long)in_sizes[1] / 2;

    float* out_ptr = (float*)d_out;                              // [N, 32]
    float* h_ptr   = (float*)d_out + (long long)N_NODES * C_DIM; // [N, 64]

    detect_kernel<<<1, 256>>>((const int*)ei);
    init_dis_kernel<<<(N_NODES + 255) / 256, 256>>>();
    convert_deg_kernel<<<2048, 256>>>(ei, E);
    gemm1_kernel<<<(N_NODES + 31) / 32, 256>>>(x, W1);
    {
        long long warps = (E + 1) / 2;                           // 2 edges per warp
        unsigned blocks = (unsigned)((warps + 7) / 8);
        scatter1_kernel<<<blocks, 256>>>(E);
    }
    fuse_kernel<<<(N_NODES + 15) / 16, 256>>>(W2, h_ptr);
    {
        long long warps = (E + 3) / 4;                           // 4 edges per warp
        unsigned blocks = (unsigned)((warps + 7) / 8);
        scatter2_kernel<<<blocks, 256>>>(E);
    }
    final_kernel<<<(unsigned)(((long long)N_NODES * C_DIM + 255) / 256), 256>>>(out_ptr);
}